// round 11
// baseline (speedup 1.0000x reference)
#include <cuda_runtime.h>
#include <cstdint>
#include <math.h>

// ---------------- problem dims ----------------
#define B_ROWS 16384
#define D_VIS  1024
#define D_H    256
#define E_NUM  4
#define G_NUM  5000
#define MAP_   128
#define SCVI_  30
#define N_GD2  (G_NUM*2)

// ---------------- tf32 mma.sync GEMM tile config ----------------
#define BM 64
#define BN 128
#define BK 32
#define NTHREADS 256
#define AS_STRIDE 36            // 8B-bank multiplicity 2 -> optimal LDS.64
#define BS_STRIDE 132           // fully distinct banks for B frags
#define AS_SIZE (BM*AS_STRIDE)  // 2304 floats
#define BS_SIZE (BK*BS_STRIDE)  // 4224 floats
#define STAGE_FLOATS (AS_SIZE + BS_SIZE)   // 6528 floats
#define SMEM_BYTES (2*STAGE_FLOATS*4)      // 52224 B; 3 CTA/SM (reg-limited)
#define MAX_TILES 260

// ---------------- scratch ----------------
__device__ float g_four[(size_t)B_ROWS*2*MAP_];
__device__ float g_z   [(size_t)B_ROWS*D_H];
__device__ float g_zr  [(size_t)B_ROWS*D_H];
__device__ float g_zf  [(size_t)B_ROWS*D_H];
__device__ float g_tpre[(size_t)B_ROWS*D_H];
__device__ float g_t   [(size_t)B_ROWS*D_H];
__device__ float g_a1  [(size_t)B_ROWS*128];
__device__ float g_f1  [(size_t)B_ROWS*64];
__device__ float g_h   [(size_t)MAX_TILES*BM*1024];
__device__ int   g_eid [B_ROWS];
__device__ float g_gate[B_ROWS];
__device__ int   g_perm[MAX_TILES*BM];
__device__ int   g_counts[E_NUM];
__device__ int   g_cursor[E_NUM];
__device__ int   g_padoff[E_NUM+1];
// pre-rounded weights
__device__ float g_w_pos[256*256];
__device__ float g_w_img[1024*256];
__device__ float g_w_e1 [E_NUM*256*1024];
__device__ float g_w_e2 [E_NUM*1024*256];
__device__ float g_w_gd1[256*256];
__device__ float g_w_gd2[256*N_GD2];
__device__ float g_w_apfh[256*192];   // packed [ap1 | fh1] N=192

// ---------------- helpers ----------------
__device__ __forceinline__ float gelu_exact(float x) {
    return 0.5f * x * (1.0f + erff(x * 0.70710678118654752440f));
}
__device__ __forceinline__ uint32_t f2tf(float f) {
    uint32_t o; asm("cvt.rna.tf32.f32 %0, %1;" : "=r"(o) : "f"(f)); return o;
}
__device__ __forceinline__ float rnd_tf(float f) { return __uint_as_float(f2tf(f)); }

__device__ __forceinline__ void mma8(float* c, const uint32_t* a, const uint32_t* b) {
    asm volatile("mma.sync.aligned.m16n8k8.row.col.f32.tf32.tf32.f32 "
        "{%0,%1,%2,%3}, {%4,%5,%6,%7}, {%8,%9}, {%0,%1,%2,%3};"
        : "+f"(c[0]), "+f"(c[1]), "+f"(c[2]), "+f"(c[3])
        : "r"(a[0]), "r"(a[1]), "r"(a[2]), "r"(a[3]), "r"(b[0]), "r"(b[1]));
}
__device__ __forceinline__ void cp_async16(float* dst_smem, const float* src, int src_bytes) {
    uint32_t d = (uint32_t)__cvta_generic_to_shared(dst_smem);
    asm volatile("cp.async.cg.shared.global [%0], [%1], 16, %2;\n"
                 :: "r"(d), "l"(src), "r"(src_bytes));
}
__device__ __forceinline__ void cp16f(float* dst_smem, const float* src) {
    uint32_t d = (uint32_t)__cvta_generic_to_shared(dst_smem);
    asm volatile("cp.async.cg.shared.global [%0], [%1], 16;\n" :: "r"(d), "l"(src));
}
__device__ __forceinline__ void cp_commit() { asm volatile("cp.async.commit_group;\n"); }
template<int N> __device__ __forceinline__ void cp_wait() {
    asm volatile("cp.async.wait_group %0;\n" :: "n"(N));
}

// ---------------- merged weight pre-round (one launch) ----------------
#define N4_POS 16384
#define N4_IMG 65536
#define N4_E1  262144
#define N4_E2  262144
#define N4_GD1 16384
#define N4_GD2 640000
#define N4_AP1 8192
#define N4_FH1 4096
#define RC0 (N4_POS)
#define RC1 (RC0+N4_IMG)
#define RC2 (RC1+N4_E1)
#define RC3 (RC2+N4_E2)
#define RC4 (RC3+N4_GD1)
#define RC5 (RC4+N4_GD2)
#define RC6 (RC5+N4_AP1)
#define RC7 (RC6+N4_FH1)

__global__ void k_round_all(const float* __restrict__ pos_W, const float* __restrict__ img_W,
                            const float* __restrict__ eW1,   const float* __restrict__ eW2,
                            const float* __restrict__ gdW1,  const float* __restrict__ gdW2,
                            const float* __restrict__ apW1,  const float* __restrict__ fhW1) {
    int i = blockIdx.x * blockDim.x + threadIdx.x;
    if (i >= RC7) return;
    const float* src; float* dst; int off; int dsti;
    if      (i < RC0) { src = pos_W; dst = g_w_pos; off = i;       dsti = off; }
    else if (i < RC1) { src = img_W; dst = g_w_img; off = i - RC0; dsti = off; }
    else if (i < RC2) { src = eW1;   dst = g_w_e1;  off = i - RC1; dsti = off; }
    else if (i < RC3) { src = eW2;   dst = g_w_e2;  off = i - RC2; dsti = off; }
    else if (i < RC4) { src = gdW1;  dst = g_w_gd1; off = i - RC3; dsti = off; }
    else if (i < RC5) { src = gdW2;  dst = g_w_gd2; off = i - RC4; dsti = off; }
    else if (i < RC6) { // ap1 [256,128] -> packed cols 0..127 of N=192
        src = apW1; dst = g_w_apfh; off = i - RC5;
        int row = off >> 5, c4 = off & 31;
        dsti = row * 48 + c4;
    }
    else { // fh1 [256,64] -> packed cols 128..191
        src = fhW1; dst = g_w_apfh; off = i - RC6;
        int row = off >> 4, c4 = off & 15;
        dsti = row * 48 + 32 + c4;
    }
    float4 v = ((const float4*)src)[off];
    v.x = rnd_tf(v.x); v.y = rnd_tf(v.y); v.z = rnd_tf(v.z); v.w = rnd_tf(v.w);
    ((float4*)dst)[dsti] = v;
}

// Load one 64x32 A tile (optional perm-gather; row<0 -> zero) and one
// 32x128 B tile (column-guarded vs N only when needed) via cp.async.
__device__ __forceinline__ void issue_tile(
    float* stage,
    const float* __restrict__ A, int lda,
    const float* __restrict__ W, int N,
    int m0, int n0, int k0, const int* __restrict__ perm)
{
    float* As = stage;
    float* Bs = stage + AS_SIZE;
    const int tid = threadIdx.x;
    // A: 64 rows x 32 floats; 4 threads/row, 2x float4 each
    int ar = tid >> 2;
    int ac = (tid & 3) * 8;
    if (perm) {
        int rowg = perm[m0 + ar];
        const float* srcA = A + (size_t)(rowg < 0 ? 0 : rowg) * lda + k0 + ac;
        int szA = (rowg >= 0) ? 16 : 0;
        cp_async16(As + ar*AS_STRIDE + ac,     srcA,     szA);
        cp_async16(As + ar*AS_STRIDE + ac + 4, srcA + 4, szA);
    } else {
        const float* srcA = A + (size_t)(m0 + ar) * lda + k0 + ac;
        cp16f(As + ar*AS_STRIDE + ac,     srcA);
        cp16f(As + ar*AS_STRIDE + ac + 4, srcA + 4);
    }
    // B: 32 rows x 128 floats; 8 threads/row, 4x float4 each
    int br = tid >> 3;
    int bc = (tid & 7) * 16;
    const float* srcB = W + (size_t)(k0 + br) * N + n0 + bc;
    if (n0 + BN <= N) {
        #pragma unroll
        for (int i = 0; i < 4; i++)
            cp16f(Bs + br*BS_STRIDE + bc + i*4, srcB + i*4);
    } else {
        #pragma unroll
        for (int i = 0; i < 4; i++) {
            int col = n0 + bc + i*4;
            int bytes = (N - col) * 4;
            bytes = bytes < 0 ? 0 : (bytes > 16 ? 16 : bytes);
            cp_async16(Bs + br*BS_STRIDE + bc + i*4, bytes > 0 ? (srcB + i*4) : W, bytes);
        }
    }
}

// 2-stage pipelined tf32 GEMM accumulate (single sync per k-tile).
// Warp grid 2(m) x 4(n), warp tile 32x32. k-slot permutation sigma(t4)=2t4,
// sigma(t4+4)=2t4+1 applied identically to A and B (result invariant).
template<bool CVTA>
__device__ __forceinline__ void gemm_tf32(
    float acc[2][4][4],
    const float* __restrict__ A, int lda, int K,
    const float* __restrict__ W, int N,
    int m0, int n0, const int* __restrict__ perm, float* sm)
{
    const int KT = K >> 5;
    issue_tile(sm, A, lda, W, N, m0, n0, 0, perm);
    cp_commit();

    const int warp = threadIdx.x >> 5, lane = threadIdx.x & 31;
    const int mw = (warp >> 2) * 32, nw = (warp & 3) * 32;
    const int g = lane >> 2, t4 = lane & 3;

    for (int kt = 0; kt < KT; kt++) {
        cp_wait<0>();
        __syncthreads();
        if (kt + 1 < KT) {
            issue_tile(sm + ((kt+1)&1)*STAGE_FLOATS, A, lda, W, N, m0, n0, (kt+1)*BK, perm);
            cp_commit();
        }
        const float* Asf = sm + (kt&1)*STAGE_FLOATS;
        const uint32_t* As = (const uint32_t*)Asf;
        const uint32_t* Bs = (const uint32_t*)(Asf + AS_SIZE);
        #pragma unroll
        for (int ks = 0; ks < BK/8; ks++) {
            const int k0s = ks * 8;
            uint32_t af[2][4], bf[4][2];
            #pragma unroll
            for (int mi = 0; mi < 2; mi++) {
                int r = mw + mi*16 + g;
                uint2 pa = *(const uint2*)(As + (r  )*AS_STRIDE + k0s + 2*t4);
                uint2 pb = *(const uint2*)(As + (r+8)*AS_STRIDE + k0s + 2*t4);
                if (CVTA) {
                    af[mi][0] = f2tf(__uint_as_float(pa.x));
                    af[mi][2] = f2tf(__uint_as_float(pa.y));
                    af[mi][1] = f2tf(__uint_as_float(pb.x));
                    af[mi][3] = f2tf(__uint_as_float(pb.y));
                } else {
                    af[mi][0] = pa.x; af[mi][2] = pa.y;
                    af[mi][1] = pb.x; af[mi][3] = pb.y;
                }
            }
            #pragma unroll
            for (int ni = 0; ni < 4; ni++) {
                int c = nw + ni*8 + g;
                bf[ni][0] = Bs[(k0s + 2*t4    )*BS_STRIDE + c];
                bf[ni][1] = Bs[(k0s + 2*t4 + 1)*BS_STRIDE + c];
            }
            #pragma unroll
            for (int mi = 0; mi < 2; mi++)
                #pragma unroll
                for (int ni = 0; ni < 4; ni++)
                    mma8(acc[mi][ni], af[mi], bf[ni]);
        }
    }
    __syncthreads();   // protect stage buffers across back-to-back calls
}

#define FRAG_IDX \
    const int warp = threadIdx.x >> 5, lane = threadIdx.x & 31; \
    const int mw = (warp >> 2) * 32, nw = (warp & 3) * 32; \
    const int g = lane >> 2, t4 = lane & 3;

// ---------------- stage kernels ----------------
__global__ void k_four(const float* __restrict__ pos, const float* __restrict__ fB) {
    int w = threadIdx.x >> 5, lane = threadIdx.x & 31;
    int row = blockIdx.x * 8 + w;
    float p0 = pos[row*3+0], p1 = pos[row*3+1], p2 = pos[row*3+2];
    #pragma unroll
    for (int i = 0; i < 4; i++) {
        int c = lane + 32*i;
        float xp = 6.283185307179586477f * (p0*fB[c] + p1*fB[MAP_+c] + p2*fB[2*MAP_+c]);
        float s, co;
        sincosf(xp, &s, &co);
        g_four[(size_t)row*256 + c]       = rnd_tf(s);
        g_four[(size_t)row*256 + 128 + c] = rnd_tf(co);
    }
}

__global__ void k_init() {
    int idx = blockIdx.x * blockDim.x + threadIdx.x;
    if (idx < MAX_TILES*BM) g_perm[idx] = -1;
    if (idx < E_NUM) { g_counts[idx] = 0; g_cursor[idx] = 0; }
}

__global__ void __launch_bounds__(NTHREADS, 3)
k_gemm_z(const float* __restrict__ vis,
         const float* __restrict__ img_b, const float* __restrict__ pos_b) {
    extern __shared__ float sm[];
    float acc[2][4][4] = {};
    int m0 = blockIdx.y * BM, n0 = blockIdx.x * BN;
    FRAG_IDX
    gemm_tf32<false>(acc, g_four, 256, 256, g_w_pos, 256, m0, n0, nullptr, sm);
    #pragma unroll
    for (int mi = 0; mi < 2; mi++)
        #pragma unroll
        for (int ni = 0; ni < 4; ni++) {
            int c0 = n0 + nw + ni*8 + t4*2;
            acc[mi][ni][0] = gelu_exact(acc[mi][ni][0] + pos_b[c0]);
            acc[mi][ni][1] = gelu_exact(acc[mi][ni][1] + pos_b[c0+1]);
            acc[mi][ni][2] = gelu_exact(acc[mi][ni][2] + pos_b[c0]);
            acc[mi][ni][3] = gelu_exact(acc[mi][ni][3] + pos_b[c0+1]);
        }
    gemm_tf32<true>(acc, vis, D_VIS, D_VIS, g_w_img, 256, m0, n0, nullptr, sm);
    #pragma unroll
    for (int mi = 0; mi < 2; mi++)
        #pragma unroll
        for (int ni = 0; ni < 4; ni++) {
            int r0 = m0 + mw + mi*16 + g, r1 = r0 + 8;
            int c0 = n0 + nw + ni*8 + t4*2, c1 = c0 + 1;
            float v00 = acc[mi][ni][0] + img_b[c0];
            float v01 = acc[mi][ni][1] + img_b[c1];
            float v10 = acc[mi][ni][2] + img_b[c0];
            float v11 = acc[mi][ni][3] + img_b[c1];
            g_z [(size_t)r0*256 + c0] = v00;  g_zr[(size_t)r0*256 + c0] = rnd_tf(v00);
            g_z [(size_t)r0*256 + c1] = v01;  g_zr[(size_t)r0*256 + c1] = rnd_tf(v01);
            g_z [(size_t)r1*256 + c0] = v10;  g_zr[(size_t)r1*256 + c0] = rnd_tf(v10);
            g_z [(size_t)r1*256 + c1] = v11;  g_zr[(size_t)r1*256 + c1] = rnd_tf(v11);
        }
}

__global__ void k_router(const float* __restrict__ grad,
                         const float* __restrict__ rW, const float* __restrict__ rb) {
    int w = threadIdx.x >> 5, lane = threadIdx.x & 31;
    int row = blockIdx.x * 8 + w;
    float4 s = make_float4(0.f,0.f,0.f,0.f);
    #pragma unroll
    for (int i = 0; i < 8; i++) {
        int k = lane + 32*i;
        float zv = g_z[(size_t)row*256 + k];
        float4 wv = *(const float4*)(rW + k*4);
        s.x = fmaf(zv, wv.x, s.x); s.y = fmaf(zv, wv.y, s.y);
        s.z = fmaf(zv, wv.z, s.z); s.w = fmaf(zv, wv.w, s.w);
    }
    #pragma unroll
    for (int off = 16; off; off >>= 1) {
        s.x += __shfl_down_sync(0xffffffffu, s.x, off);
        s.y += __shfl_down_sync(0xffffffffu, s.y, off);
        s.z += __shfl_down_sync(0xffffffffu, s.z, off);
        s.w += __shfl_down_sync(0xffffffffu, s.w, off);
    }
    if (lane == 0) {
        float gv = grad[row];
        float4 wg = *(const float4*)(rW + 256*4);
        float l0 = s.x + gv*wg.x + rb[0];
        float l1 = s.y + gv*wg.y + rb[1];
        float l2 = s.z + gv*wg.z + rb[2];
        float l3 = s.w + gv*wg.w + rb[3];
        float m = l0; int am = 0;
        if (l1 > m) { m = l1; am = 1; }
        if (l2 > m) { m = l2; am = 2; }
        if (l3 > m) { m = l3; am = 3; }
        float sum = expf(l0-m) + expf(l1-m) + expf(l2-m) + expf(l3-m);
        g_eid[row]  = am;
        g_gate[row] = 1.0f / sum;
        atomicAdd(&g_counts[am], 1);
    }
}

__global__ void k_offsets() {
    int off = 0;
    for (int e = 0; e < E_NUM; e++) {
        g_padoff[e] = off;
        off += ((g_counts[e] + BM - 1) / BM) * BM;
    }
    g_padoff[E_NUM] = off;
}

__global__ void k_scatter() {
    int row = blockIdx.x * 256 + threadIdx.x;
    int e = g_eid[row];
    int slot = g_padoff[e] + atomicAdd(&g_cursor[e], 1);
    g_perm[slot] = row;
}

__device__ __forceinline__ int tile_expert(int m0) {
    int e = 0;
    while (e < E_NUM-1 && m0 >= g_padoff[e+1]) e++;
    return e;
}

__global__ void __launch_bounds__(NTHREADS, 3)
k_moe1(const float* __restrict__ eb1) {
    int m0 = blockIdx.y * BM;
    if (m0 >= g_padoff[E_NUM]) return;
    extern __shared__ float sm[];
    int e = tile_expert(m0);
    const float* W1 = g_w_e1 + (size_t)e * 256 * 1024;
    float acc[2][4][4] = {};
    int n0 = blockIdx.x * BN;
    gemm_tf32<false>(acc, g_zr, 256, 256, W1, 1024, m0, n0, g_perm, sm);
    FRAG_IDX
    #pragma unroll
    for (int mi = 0; mi < 2; mi++)
        #pragma unroll
        for (int ni = 0; ni < 4; ni++) {
            int r0 = m0 + mw + mi*16 + g, r1 = r0 + 8;
            int c0 = n0 + nw + ni*8 + t4*2, c1 = c0 + 1;
            g_h[(size_t)r0*1024 + c0] = rnd_tf(gelu_exact(acc[mi][ni][0] + eb1[e*1024 + c0]));
            g_h[(size_t)r0*1024 + c1] = rnd_tf(gelu_exact(acc[mi][ni][1] + eb1[e*1024 + c1]));
            g_h[(size_t)r1*1024 + c0] = rnd_tf(gelu_exact(acc[mi][ni][2] + eb1[e*1024 + c0]));
            g_h[(size_t)r1*1024 + c1] = rnd_tf(gelu_exact(acc[mi][ni][3] + eb1[e*1024 + c1]));
        }
}

__global__ void __launch_bounds__(NTHREADS, 3)
k_moe2(const float* __restrict__ eb2) {
    int m0 = blockIdx.y * BM;
    if (m0 >= g_padoff[E_NUM]) return;
    extern __shared__ float sm[];
    int e = tile_expert(m0);
    const float* W2 = g_w_e2 + (size_t)e * 1024 * 256;
    float acc[2][4][4] = {};
    int n0 = blockIdx.x * BN;
    gemm_tf32<false>(acc, g_h, 1024, 1024, W2, 256, m0, n0, nullptr, sm);
    FRAG_IDX
    #pragma unroll
    for (int mi = 0; mi < 2; mi++)
        #pragma unroll
        for (int ni = 0; ni < 4; ni++) {
            int s0 = m0 + mw + mi*16 + g, s1 = s0 + 8;
            int c0 = n0 + nw + ni*8 + t4*2, c1 = c0 + 1;
            int r0 = g_perm[s0], r1 = g_perm[s1];
            if (r0 >= 0) {
                float gate = g_gate[r0];
                g_zf[(size_t)r0*256 + c0] = rnd_tf(g_z[(size_t)r0*256 + c0] + gate*(acc[mi][ni][0] + eb2[e*256 + c0]));
                g_zf[(size_t)r0*256 + c1] = rnd_tf(g_z[(size_t)r0*256 + c1] + gate*(acc[mi][ni][1] + eb2[e*256 + c1]));
            }
            if (r1 >= 0) {
                float gate = g_gate[r1];
                g_zf[(size_t)r1*256 + c0] = rnd_tf(g_z[(size_t)r1*256 + c0] + gate*(acc[mi][ni][2] + eb2[e*256 + c0]));
                g_zf[(size_t)r1*256 + c1] = rnd_tf(g_z[(size_t)r1*256 + c1] + gate*(acc[mi][ni][3] + eb2[e*256 + c1]));
            }
        }
}

__global__ void __launch_bounds__(NTHREADS, 3)
k_tpre(const float* __restrict__ b) {
    extern __shared__ float sm[];
    float acc[2][4][4] = {};
    int m0 = blockIdx.y * BM, n0 = blockIdx.x * BN;
    gemm_tf32<false>(acc, g_zf, 256, 256, g_w_gd1, 256, m0, n0, nullptr, sm);
    FRAG_IDX
    #pragma unroll
    for (int mi = 0; mi < 2; mi++)
        #pragma unroll
        for (int ni = 0; ni < 4; ni++) {
            int r0 = m0 + mw + mi*16 + g, r1 = r0 + 8;
            int c0 = n0 + nw + ni*8 + t4*2, c1 = c0 + 1;
            g_tpre[(size_t)r0*256 + c0] = acc[mi][ni][0] + b[c0];
            g_tpre[(size_t)r0*256 + c1] = acc[mi][ni][1] + b[c1];
            g_tpre[(size_t)r1*256 + c0] = acc[mi][ni][2] + b[c0];
            g_tpre[(size_t)r1*256 + c1] = acc[mi][ni][3] + b[c1];
        }
}

__global__ void k_ln(const float* __restrict__ gam, const float* __restrict__ beta) {
    int w = threadIdx.x >> 5, lane = threadIdx.x & 31;
    int row = blockIdx.x * 8 + w;
    float v[8]; float s = 0.f;
    #pragma unroll
    for (int i = 0; i < 8; i++) {
        v[i] = g_tpre[(size_t)row*256 + lane + 32*i];
        s += v[i];
    }
    #pragma unroll
    for (int off = 16; off; off >>= 1) s += __shfl_xor_sync(0xffffffffu, s, off);
    float mean = s * (1.f/256.f);
    float s2 = 0.f;
    #pragma unroll
    for (int i = 0; i < 8; i++) { float d = v[i] - mean; s2 = fmaf(d, d, s2); }
    #pragma unroll
    for (int off = 16; off; off >>= 1) s2 += __shfl_xor_sync(0xffffffffu, s2, off);
    float rs = rsqrtf(s2 * (1.f/256.f) + 1e-5f);
    #pragma unroll
    for (int i = 0; i < 8; i++) {
        int k = lane + 32*i;
        g_t[(size_t)row*256 + k] = rnd_tf(gelu_exact(gam[k] * (v[i] - mean) * rs + beta[k]));
    }
}

__device__ __forceinline__ void gd2_emit(float* __restrict__ out,
                                         const float* __restrict__ lib,
                                         const float* __restrict__ b2,
                                         int row, int col, float v) {
    if (col >= N_GD2) return;
    v += b2[col];
    float sp = (v > 20.f) ? v : log1pf(expf(v));
    int gi = col >> 1;
    if (col & 1) out[(size_t)B_ROWS*G_NUM + (size_t)row*G_NUM + gi] = sp + 1e-6f;
    else         out[(size_t)row*G_NUM + gi] = sp * lib[row] + 1e-6f;
}

__global__ void __launch_bounds__(NTHREADS, 3)
k_gd2(const float* __restrict__ b2,
      const float* __restrict__ lib, float* __restrict__ out) {
    extern __shared__ float sm[];
    float acc[2][4][4] = {};
    int m0 = blockIdx.y * BM, n0 = blockIdx.x * BN;
    gemm_tf32<false>(acc, g_t, 256, 256, g_w_gd2, N_GD2, m0, n0, nullptr, sm);
    FRAG_IDX
    #pragma unroll
    for (int mi = 0; mi < 2; mi++)
        #pragma unroll
        for (int ni = 0; ni < 4; ni++) {
            int r0 = m0 + mw + mi*16 + g, r1 = r0 + 8;
            int c0 = n0 + nw + ni*8 + t4*2, c1 = c0 + 1;
            gd2_emit(out, lib, b2, r0, c0, acc[mi][ni][0]);
            gd2_emit(out, lib, b2, r0, c1, acc[mi][ni][1]);
            gd2_emit(out, lib, b2, r1, c0, acc[mi][ni][2]);
            gd2_emit(out, lib, b2, r1, c1, acc[mi][ni][3]);
        }
}

// merged align + func hidden: N=192 packed weights
__global__ void __launch_bounds__(NTHREADS, 3)
k_apfh(const float* __restrict__ apb, const float* __restrict__ fhb) {
    extern __shared__ float sm[];
    float acc[2][4][4] = {};
    int m0 = blockIdx.y * BM, n0 = blockIdx.x * BN;
    gemm_tf32<false>(acc, g_zf, 256, 256, g_w_apfh, 192, m0, n0, nullptr, sm);
    FRAG_IDX
    #pragma unroll
    for (int mi = 0; mi < 2; mi++)
        #pragma unroll
        for (int ni = 0; ni < 4; ni++) {
            int r0 = m0 + mw + mi*16 + g, r1 = r0 + 8;
            int c0 = n0 + nw + ni*8 + t4*2, c1 = c0 + 1;
            #pragma unroll
            for (int q = 0; q < 4; q++) {
                int r = (q & 2) ? r1 : r0;
                int c = (q & 1) ? c1 : c0;
                float v = acc[mi][ni][q];
                if (c < 128)
                    g_a1[(size_t)r*128 + c] = gelu_exact(v + apb[c]);
                else if (c < 192)
                    g_f1[(size_t)r*64 + (c - 128)] = gelu_exact(v + fhb[c - 128]);
            }
        }
}

__global__ void k_ap2(const float* __restrict__ W2, const float* __restrict__ b2,
                      float* __restrict__ out) {
    __shared__ float Ws[128*SCVI_];
    __shared__ float bs[SCVI_];
    for (int i = threadIdx.x; i < 128*SCVI_; i += 256) Ws[i] = W2[i];
    if (threadIdx.x < SCVI_) bs[threadIdx.x] = b2[threadIdx.x];
    __syncthreads();
    int w = threadIdx.x >> 5, lane = threadIdx.x & 31;
    int row = blockIdx.x * 8 + w;
    float a[4];
    #pragma unroll
    for (int i = 0; i < 4; i++) a[i] = g_a1[(size_t)row*128 + lane + 32*i];
    const size_t ALIGN_OFF = 2ull * B_ROWS * G_NUM + B_ROWS;
    for (int c = 0; c < SCVI_; c++) {
        float s = 0.f;
        #pragma unroll
        for (int i = 0; i < 4; i++) s = fmaf(a[i], Ws[(lane + 32*i)*SCVI_ + c], s);
        #pragma unroll
        for (int off = 16; off; off >>= 1) s += __shfl_down_sync(0xffffffffu, s, off);
        if (lane == 0) out[ALIGN_OFF + (size_t)row*SCVI_ + c] = s + bs[c];
    }
}

__global__ void k_fh2(const float* __restrict__ W2, const float* __restrict__ b2,
                      float* __restrict__ out) {
    int w = threadIdx.x >> 5, lane = threadIdx.x & 31;
    int row = blockIdx.x * 8 + w;
    float v = g_f1[(size_t)row*64 + lane] * W2[lane]
            + g_f1[(size_t)row*64 + lane + 32] * W2[lane + 32];
    #pragma unroll
    for (int off = 16; off; off >>= 1) v += __shfl_down_sync(0xffffffffu, v, off);
    if (lane == 0) {
        const size_t FUNC_OFF = 2ull * B_ROWS * G_NUM;
        out[FUNC_OFF + row] = 1.f / (1.f + expf(-(v + b2[0])));
    }
}

// ---------------- launch ----------------
extern "C" void kernel_launch(void* const* d_in, const int* in_sizes, int n_in,
                              void* d_out, int out_size) {
    const float* vis   = (const float*)d_in[0];
    const float* pos   = (const float*)d_in[1];
    const float* grad  = (const float*)d_in[2];
    const float* lib   = (const float*)d_in[3];
    const float* fB    = (const float*)d_in[4];
    const float* img_W = (const float*)d_in[5];
    const float* img_b = (const float*)d_in[6];
    const float* pos_W = (const float*)d_in[7];
    const float* pos_b = (const float*)d_in[8];
    const float* rW    = (const float*)d_in[9];
    const float* rb    = (const float*)d_in[10];
    const float* eW1   = (const float*)d_in[11];
    const float* eb1   = (const float*)d_in[12];
    const float* eW2   = (const float*)d_in[13];
    const float* eb2   = (const float*)d_in[14];
    const float* gdW1  = (const float*)d_in[15];
    const float* gdb1  = (const float*)d_in[16];
    const float* gdg   = (const float*)d_in[17];
    const float* gdbe  = (const float*)d_in[18];
    const float* gdW2  = (const float*)d_in[19];
    const float* gdb2  = (const float*)d_in[20];
    const float* apW1  = (const float*)d_in[21];
    const float* apb1  = (const float*)d_in[22];
    const float* apW2  = (const float*)d_in[23];
    const float* apb2  = (const float*)d_in[24];
    const float* fhW1  = (const float*)d_in[25];
    const float* fhb1  = (const float*)d_in[26];
    const float* fhW2  = (const float*)d_in[27];
    const float* fhb2  = (const float*)d_in[28];
    float* out = (float*)d_out;

    static const int SM = SMEM_BYTES;
    cudaFuncSetAttribute(k_gemm_z, cudaFuncAttributeMaxDynamicSharedMemorySize, SM);
    cudaFuncSetAttribute(k_moe1,   cudaFuncAttributeMaxDynamicSharedMemorySize, SM);
    cudaFuncSetAttribute(k_moe2,   cudaFuncAttributeMaxDynamicSharedMemorySize, SM);
    cudaFuncSetAttribute(k_tpre,   cudaFuncAttributeMaxDynamicSharedMemorySize, SM);
    cudaFuncSetAttribute(k_gd2,    cudaFuncAttributeMaxDynamicSharedMemorySize, SM);
    cudaFuncSetAttribute(k_apfh,   cudaFuncAttributeMaxDynamicSharedMemorySize, SM);

    k_round_all<<<(RC7 + 255)/256, 256>>>(pos_W, img_W, eW1, eW2, gdW1, gdW2, apW1, fhW1);

    k_four   <<<B_ROWS/8, 256>>>(pos, fB);
    k_init   <<<(MAX_TILES*BM + 255)/256, 256>>>();
    k_gemm_z <<<dim3(2, B_ROWS/BM), NTHREADS, SM>>>(vis, img_b, pos_b);
    k_router <<<B_ROWS/8, 256>>>(grad, rW, rb);
    k_offsets<<<1,1>>>();
    k_scatter<<<B_ROWS/256, 256>>>();
    k_moe1   <<<dim3(8, MAX_TILES), NTHREADS, SM>>>(eb1);
    k_moe2   <<<dim3(2, MAX_TILES), NTHREADS, SM>>>(eb2);
    k_tpre   <<<dim3(2, B_ROWS/BM), NTHREADS, SM>>>(gdb1);
    k_ln     <<<B_ROWS/8, 256>>>(gdg, gdbe);
    k_gd2    <<<dim3((N_GD2 + BN - 1)/BN, B_ROWS/BM), NTHREADS, SM>>>(gdb2, lib, out);
    k_apfh   <<<dim3(2, B_ROWS/BM), NTHREADS, SM>>>(apb1, fhb1);
    k_ap2    <<<B_ROWS/8, 256>>>(apW2, apb2, out);
    k_fh2    <<<B_ROWS/8, 256>>>(fhW2, fhb2, out);
}

// round 12
// speedup vs baseline: 1.1085x; 1.1085x over previous
#include <cuda_runtime.h>
#include <cstdint>
#include <math.h>

// ---------------- problem dims ----------------
#define B_ROWS 16384
#define D_VIS  1024
#define D_H    256
#define E_NUM  4
#define G_NUM  5000
#define MAP_   128
#define SCVI_  30
#define N_GD2  (G_NUM*2)

// ---------------- tf32 mma.sync GEMM tile config (R10 geometry) ----------------
#define BM 128
#define BN 128
#define BK 32
#define STAGES 3
#define NTHREADS 256
#define AS_STRIDE 40            // %32==8 -> conflict-free LDS.64 A frags
#define BS_STRIDE 132           // %32==4 -> conflict-free B frags under 2t4 rows
#define AS_SIZE (BM*AS_STRIDE)  // 5120 floats
#define BS_SIZE (BK*BS_STRIDE)  // 4224 floats
#define STAGE_FLOATS (AS_SIZE + BS_SIZE)          // 9344 floats
#define SMEM_BYTES (STAGES*STAGE_FLOATS*4)        // 112128 B -> 2 CTA/SM
#define MAX_TILES 132
#define ES_STRIDE 132           // gd2 epilogue staging stride

// ---------------- scratch ----------------
__device__ float g_four[(size_t)B_ROWS*2*MAP_];
__device__ float g_z   [(size_t)B_ROWS*D_H];
__device__ float g_zr  [(size_t)B_ROWS*D_H];
__device__ float g_zf  [(size_t)B_ROWS*D_H];
__device__ float g_tpre[(size_t)B_ROWS*D_H];
__device__ float g_t   [(size_t)B_ROWS*D_H];
__device__ float g_a1  [(size_t)B_ROWS*128];
__device__ float g_f1  [(size_t)B_ROWS*64];
__device__ float g_h   [(size_t)MAX_TILES*BM*1024];
__device__ int   g_eid [B_ROWS];
__device__ float g_gate[B_ROWS];
__device__ int   g_perm[MAX_TILES*BM];
__device__ int   g_counts[E_NUM];
__device__ int   g_cursor[E_NUM];
__device__ int   g_padoff[E_NUM+1];
// pre-rounded weights
__device__ float g_w_pos[256*256];
__device__ float g_w_img[1024*256];
__device__ float g_w_e1 [E_NUM*256*1024];
__device__ float g_w_e2 [E_NUM*1024*256];
__device__ float g_w_gd1[256*256];
__device__ float g_w_gd2[256*N_GD2];
__device__ float g_w_apfh[256*192];   // packed [ap1 | fh1] N=192

// ---------------- helpers ----------------
__device__ __forceinline__ float gelu_exact(float x) {
    return 0.5f * x * (1.0f + erff(x * 0.70710678118654752440f));
}
__device__ __forceinline__ uint32_t f2tf(float f) {
    uint32_t o; asm("cvt.rna.tf32.f32 %0, %1;" : "=r"(o) : "f"(f)); return o;
}
__device__ __forceinline__ float rnd_tf(float f) { return __uint_as_float(f2tf(f)); }

__device__ __forceinline__ void mma8(float* c, const uint32_t* a, const uint32_t* b) {
    asm volatile("mma.sync.aligned.m16n8k8.row.col.f32.tf32.tf32.f32 "
        "{%0,%1,%2,%3}, {%4,%5,%6,%7}, {%8,%9}, {%0,%1,%2,%3};"
        : "+f"(c[0]), "+f"(c[1]), "+f"(c[2]), "+f"(c[3])
        : "r"(a[0]), "r"(a[1]), "r"(a[2]), "r"(a[3]), "r"(b[0]), "r"(b[1]));
}
__device__ __forceinline__ void cp_async16(float* dst_smem, const float* src, int src_bytes) {
    uint32_t d = (uint32_t)__cvta_generic_to_shared(dst_smem);
    asm volatile("cp.async.cg.shared.global [%0], [%1], 16, %2;\n"
                 :: "r"(d), "l"(src), "r"(src_bytes));
}
__device__ __forceinline__ void cp16f(float* dst_smem, const float* src) {
    uint32_t d = (uint32_t)__cvta_generic_to_shared(dst_smem);
    asm volatile("cp.async.cg.shared.global [%0], [%1], 16;\n" :: "r"(d), "l"(src));
}
__device__ __forceinline__ void cp_commit() { asm volatile("cp.async.commit_group;\n"); }
template<int N> __device__ __forceinline__ void cp_wait() {
    asm volatile("cp.async.wait_group %0;\n" :: "n"(N));
}

// ---------------- merged weight pre-round (one launch) ----------------
#define N4_POS 16384
#define N4_IMG 65536
#define N4_E1  262144
#define N4_E2  262144
#define N4_GD1 16384
#define N4_GD2 640000
#define N4_AP1 8192
#define N4_FH1 4096
#define RC0 (N4_POS)
#define RC1 (RC0+N4_IMG)
#define RC2 (RC1+N4_E1)
#define RC3 (RC2+N4_E2)
#define RC4 (RC3+N4_GD1)
#define RC5 (RC4+N4_GD2)
#define RC6 (RC5+N4_AP1)
#define RC7 (RC6+N4_FH1)

__global__ void k_round_all(const float* __restrict__ pos_W, const float* __restrict__ img_W,
                            const float* __restrict__ eW1,   const float* __restrict__ eW2,
                            const float* __restrict__ gdW1,  const float* __restrict__ gdW2,
                            const float* __restrict__ apW1,  const float* __restrict__ fhW1) {
    int i = blockIdx.x * blockDim.x + threadIdx.x;
    if (i >= RC7) return;
    const float* src; float* dst; int off; int dsti;
    if      (i < RC0) { src = pos_W; dst = g_w_pos; off = i;       dsti = off; }
    else if (i < RC1) { src = img_W; dst = g_w_img; off = i - RC0; dsti = off; }
    else if (i < RC2) { src = eW1;   dst = g_w_e1;  off = i - RC1; dsti = off; }
    else if (i < RC3) { src = eW2;   dst = g_w_e2;  off = i - RC2; dsti = off; }
    else if (i < RC4) { src = gdW1;  dst = g_w_gd1; off = i - RC3; dsti = off; }
    else if (i < RC5) { src = gdW2;  dst = g_w_gd2; off = i - RC4; dsti = off; }
    else if (i < RC6) { // ap1 [256,128] -> packed cols 0..127 of N=192
        src = apW1; dst = g_w_apfh; off = i - RC5;
        int row = off >> 5, c4 = off & 31;
        dsti = row * 48 + c4;
    }
    else { // fh1 [256,64] -> packed cols 128..191
        src = fhW1; dst = g_w_apfh; off = i - RC6;
        int row = off >> 4, c4 = off & 15;
        dsti = row * 48 + 32 + c4;
    }
    float4 v = ((const float4*)src)[off];
    v.x = rnd_tf(v.x); v.y = rnd_tf(v.y); v.z = rnd_tf(v.z); v.w = rnd_tf(v.w);
    ((float4*)dst)[dsti] = v;
}

// Load one 128x32 A tile (optional perm-gather; row<0 -> zero) and one
// 32x128 B tile (column-guarded vs N only when needed) via cp.async.
__device__ __forceinline__ void issue_tile(
    float* stage,
    const float* __restrict__ A, int lda,
    const float* __restrict__ W, int N,
    int m0, int n0, int k0, const int* __restrict__ perm)
{
    float* As = stage;
    float* Bs = stage + AS_SIZE;
    const int tid = threadIdx.x;
    int ar = tid >> 1;
    int ac = (tid & 1) * 16;
    if (perm) {
        int rowg = perm[m0 + ar];
        const float* srcA = A + (size_t)(rowg < 0 ? 0 : rowg) * lda + k0 + ac;
        int szA = (rowg >= 0) ? 16 : 0;
        #pragma unroll
        for (int i = 0; i < 4; i++)
            cp_async16(As + ar*AS_STRIDE + ac + i*4, srcA + i*4, szA);
    } else {
        const float* srcA = A + (size_t)(m0 + ar) * lda + k0 + ac;
        #pragma unroll
        for (int i = 0; i < 4; i++)
            cp16f(As + ar*AS_STRIDE + ac + i*4, srcA + i*4);
    }
    int br = tid >> 3;
    int bc = (tid & 7) * 16;
    const float* srcB = W + (size_t)(k0 + br) * N + n0 + bc;
    if (n0 + BN <= N) {
        #pragma unroll
        for (int i = 0; i < 4; i++)
            cp16f(Bs + br*BS_STRIDE + bc + i*4, srcB + i*4);
    } else {
        #pragma unroll
        for (int i = 0; i < 4; i++) {
            int col = n0 + bc + i*4;
            int bytes = (N - col) * 4;
            bytes = bytes < 0 ? 0 : (bytes > 16 ? 16 : bytes);
            cp_async16(Bs + br*BS_STRIDE + bc + i*4, bytes > 0 ? (srcB + i*4) : W, bytes);
        }
    }
}

// Pipelined tf32 GEMM accumulate (single __syncthreads per k-tile).
// Warp grid 2x4, warp tile 64x32. k-slot permutation sigma(t4)=2t4 /
// sigma(t4+4)=2t4+1 applied identically on A and B (result invariant).
template<bool CVTA>
__device__ __forceinline__ void gemm_tf32(
    float acc[4][4][4],
    const float* __restrict__ A, int lda, int K,
    const float* __restrict__ W, int N,
    int m0, int n0, const int* __restrict__ perm, float* sm)
{
    const int KT = K >> 5;
    #pragma unroll
    for (int s = 0; s < STAGES-1; s++) {
        if (s < KT) issue_tile(sm + s*STAGE_FLOATS, A, lda, W, N, m0, n0, s*BK, perm);
        cp_commit();
    }
    cp_wait<STAGES-2>();
    __syncthreads();

    const int warp = threadIdx.x >> 5, lane = threadIdx.x & 31;
    const int mw = (warp >> 2) * 64, nw = (warp & 3) * 32;
    const int g = lane >> 2, t4 = lane & 3;

    for (int kt = 0; kt < KT; kt++) {
        const float* Asf = sm + (kt%STAGES)*STAGE_FLOATS;
        const uint32_t* As = (const uint32_t*)Asf;
        const uint32_t* Bs = (const uint32_t*)(Asf + AS_SIZE);
        #pragma unroll
        for (int ks = 0; ks < BK/8; ks++) {
            const int k0s = ks * 8;
            uint32_t af[4][4], bf[4][2];
            #pragma unroll
            for (int mi = 0; mi < 4; mi++) {
                int r = mw + mi*16 + g;
                uint2 pa = *(const uint2*)(As + (r  )*AS_STRIDE + k0s + 2*t4);
                uint2 pb = *(const uint2*)(As + (r+8)*AS_STRIDE + k0s + 2*t4);
                if (CVTA) {
                    af[mi][0] = f2tf(__uint_as_float(pa.x));
                    af[mi][2] = f2tf(__uint_as_float(pa.y));
                    af[mi][1] = f2tf(__uint_as_float(pb.x));
                    af[mi][3] = f2tf(__uint_as_float(pb.y));
                } else {
                    af[mi][0] = pa.x; af[mi][2] = pa.y;
                    af[mi][1] = pb.x; af[mi][3] = pb.y;
                }
            }
            #pragma unroll
            for (int ni = 0; ni < 4; ni++) {
                int c = nw + ni*8 + g;
                bf[ni][0] = Bs[(k0s + 2*t4    )*BS_STRIDE + c];
                bf[ni][1] = Bs[(k0s + 2*t4 + 1)*BS_STRIDE + c];
            }
            #pragma unroll
            for (int mi = 0; mi < 4; mi++)
                #pragma unroll
                for (int ni = 0; ni < 4; ni++)
                    mma8(acc[mi][ni], af[mi], bf[ni]);
        }
        int pre = kt + STAGES - 1;
        if (pre < KT) issue_tile(sm + (pre%STAGES)*STAGE_FLOATS, A, lda, W, N, m0, n0, pre*BK, perm);
        cp_commit();
        cp_wait<STAGES-2>();
        __syncthreads();
    }
}

#define FRAG_IDX \
    const int warp = threadIdx.x >> 5, lane = threadIdx.x & 31; \
    const int mw = (warp >> 2) * 64, nw = (warp & 3) * 32; \
    const int g = lane >> 2, t4 = lane & 3;

// ---------------- stage kernels ----------------
// k_four also performs the perm/counter init (folded k_init)
__global__ void k_four(const float* __restrict__ pos, const float* __restrict__ fB) {
    int gtid = blockIdx.x * 256 + threadIdx.x;
    if (gtid < MAX_TILES*BM) g_perm[gtid] = -1;
    if (gtid < E_NUM) { g_counts[gtid] = 0; g_cursor[gtid] = 0; }

    int w = threadIdx.x >> 5, lane = threadIdx.x & 31;
    int row = blockIdx.x * 8 + w;
    float p0 = pos[row*3+0], p1 = pos[row*3+1], p2 = pos[row*3+2];
    #pragma unroll
    for (int i = 0; i < 4; i++) {
        int c = lane + 32*i;
        float xp = 6.283185307179586477f * (p0*fB[c] + p1*fB[MAP_+c] + p2*fB[2*MAP_+c]);
        float s, co;
        sincosf(xp, &s, &co);
        g_four[(size_t)row*256 + c]       = rnd_tf(s);
        g_four[(size_t)row*256 + 128 + c] = rnd_tf(co);
    }
}

__global__ void __launch_bounds__(NTHREADS, 2)
k_gemm_z(const float* __restrict__ vis,
         const float* __restrict__ img_b, const float* __restrict__ pos_b) {
    extern __shared__ float sm[];
    float acc[4][4][4] = {};
    int m0 = blockIdx.y * BM, n0 = blockIdx.x * BN;
    FRAG_IDX
    gemm_tf32<false>(acc, g_four, 256, 256, g_w_pos, 256, m0, n0, nullptr, sm);
    #pragma unroll
    for (int mi = 0; mi < 4; mi++)
        #pragma unroll
        for (int ni = 0; ni < 4; ni++) {
            int c0 = n0 + nw + ni*8 + t4*2;
            acc[mi][ni][0] = gelu_exact(acc[mi][ni][0] + pos_b[c0]);
            acc[mi][ni][1] = gelu_exact(acc[mi][ni][1] + pos_b[c0+1]);
            acc[mi][ni][2] = gelu_exact(acc[mi][ni][2] + pos_b[c0]);
            acc[mi][ni][3] = gelu_exact(acc[mi][ni][3] + pos_b[c0+1]);
        }
    gemm_tf32<true>(acc, vis, D_VIS, D_VIS, g_w_img, 256, m0, n0, nullptr, sm);
    #pragma unroll
    for (int mi = 0; mi < 4; mi++)
        #pragma unroll
        for (int ni = 0; ni < 4; ni++) {
            int r0 = m0 + mw + mi*16 + g, r1 = r0 + 8;
            int c0 = n0 + nw + ni*8 + t4*2, c1 = c0 + 1;
            float v00 = acc[mi][ni][0] + img_b[c0];
            float v01 = acc[mi][ni][1] + img_b[c1];
            float v10 = acc[mi][ni][2] + img_b[c0];
            float v11 = acc[mi][ni][3] + img_b[c1];
            g_z [(size_t)r0*256 + c0] = v00;  g_zr[(size_t)r0*256 + c0] = rnd_tf(v00);
            g_z [(size_t)r0*256 + c1] = v01;  g_zr[(size_t)r0*256 + c1] = rnd_tf(v01);
            g_z [(size_t)r1*256 + c0] = v10;  g_zr[(size_t)r1*256 + c0] = rnd_tf(v10);
            g_z [(size_t)r1*256 + c1] = v11;  g_zr[(size_t)r1*256 + c1] = rnd_tf(v11);
        }
}

__global__ void k_router(const float* __restrict__ grad,
                         const float* __restrict__ rW, const float* __restrict__ rb) {
    int w = threadIdx.x >> 5, lane = threadIdx.x & 31;
    int row = blockIdx.x * 8 + w;
    float4 s = make_float4(0.f,0.f,0.f,0.f);
    #pragma unroll
    for (int i = 0; i < 8; i++) {
        int k = lane + 32*i;
        float zv = g_z[(size_t)row*256 + k];
        float4 wv = *(const float4*)(rW + k*4);
        s.x = fmaf(zv, wv.x, s.x); s.y = fmaf(zv, wv.y, s.y);
        s.z = fmaf(zv, wv.z, s.z); s.w = fmaf(zv, wv.w, s.w);
    }
    #pragma unroll
    for (int off = 16; off; off >>= 1) {
        s.x += __shfl_down_sync(0xffffffffu, s.x, off);
        s.y += __shfl_down_sync(0xffffffffu, s.y, off);
        s.z += __shfl_down_sync(0xffffffffu, s.z, off);
        s.w += __shfl_down_sync(0xffffffffu, s.w, off);
    }
    if (lane == 0) {
        float gv = grad[row];
        float4 wg = *(const float4*)(rW + 256*4);
        float l0 = s.x + gv*wg.x + rb[0];
        float l1 = s.y + gv*wg.y + rb[1];
        float l2 = s.z + gv*wg.z + rb[2];
        float l3 = s.w + gv*wg.w + rb[3];
        float m = l0; int am = 0;
        if (l1 > m) { m = l1; am = 1; }
        if (l2 > m) { m = l2; am = 2; }
        if (l3 > m) { m = l3; am = 3; }
        float sum = expf(l0-m) + expf(l1-m) + expf(l2-m) + expf(l3-m);
        g_eid[row]  = am;
        g_gate[row] = 1.0f / sum;
        atomicAdd(&g_counts[am], 1);
    }
}

__global__ void k_offsets() {
    int off = 0;
    for (int e = 0; e < E_NUM; e++) {
        g_padoff[e] = off;
        off += ((g_counts[e] + BM - 1) / BM) * BM;
    }
    g_padoff[E_NUM] = off;
}

__global__ void k_scatter() {
    int row = blockIdx.x * 256 + threadIdx.x;
    int e = g_eid[row];
    int slot = g_padoff[e] + atomicAdd(&g_cursor[e], 1);
    g_perm[slot] = row;
}

__device__ __forceinline__ int tile_expert(int m0) {
    int e = 0;
    while (e < E_NUM-1 && m0 >= g_padoff[e+1]) e++;
    return e;
}

__global__ void __launch_bounds__(NTHREADS, 2)
k_moe1(const float* __restrict__ eb1) {
    int m0 = blockIdx.y * BM;
    if (m0 >= g_padoff[E_NUM]) return;
    extern __shared__ float sm[];
    int e = tile_expert(m0);
    const float* W1 = g_w_e1 + (size_t)e * 256 * 1024;
    float acc[4][4][4] = {};
    int n0 = blockIdx.x * BN;
    gemm_tf32<false>(acc, g_zr, 256, 256, W1, 1024, m0, n0, g_perm, sm);
    FRAG_IDX
    #pragma unroll
    for (int mi = 0; mi < 4; mi++)
        #pragma unroll
        for (int ni = 0; ni < 4; ni++) {
            int r0 = m0 + mw + mi*16 + g, r1 = r0 + 8;
            int c0 = n0 + nw + ni*8 + t4*2, c1 = c0 + 1;
            g_h[(size_t)r0*1024 + c0] = rnd_tf(gelu_exact(acc[mi][ni][0] + eb1[e*1024 + c0]));
            g_h[(size_t)r0*1024 + c1] = rnd_tf(gelu_exact(acc[mi][ni][1] + eb1[e*1024 + c1]));
            g_h[(size_t)r1*1024 + c0] = rnd_tf(gelu_exact(acc[mi][ni][2] + eb1[e*1024 + c0]));
            g_h[(size_t)r1*1024 + c1] = rnd_tf(gelu_exact(acc[mi][ni][3] + eb1[e*1024 + c1]));
        }
}

__global__ void __launch_bounds__(NTHREADS, 2)
k_moe2(const float* __restrict__ eb2) {
    int m0 = blockIdx.y * BM;
    if (m0 >= g_padoff[E_NUM]) return;
    extern __shared__ float sm[];
    int e = tile_expert(m0);
    const float* W2 = g_w_e2 + (size_t)e * 1024 * 256;
    float acc[4][4][4] = {};
    int n0 = blockIdx.x * BN;
    gemm_tf32<false>(acc, g_h, 1024, 1024, W2, 256, m0, n0, nullptr, sm);
    FRAG_IDX
    #pragma unroll
    for (int mi = 0; mi < 4; mi++)
        #pragma unroll
        for (int ni = 0; ni < 4; ni++) {
            int s0 = m0 + mw + mi*16 + g, s1 = s0 + 8;
            int c0 = n0 + nw + ni*8 + t4*2, c1 = c0 + 1;
            int r0 = g_perm[s0], r1 = g_perm[s1];
            if (r0 >= 0) {
                float gate = g_gate[r0];
                g_zf[(size_t)r0*256 + c0] = rnd_tf(g_z[(size_t)r0*256 + c0] + gate*(acc[mi][ni][0] + eb2[e*256 + c0]));
                g_zf[(size_t)r0*256 + c1] = rnd_tf(g_z[(size_t)r0*256 + c1] + gate*(acc[mi][ni][1] + eb2[e*256 + c1]));
            }
            if (r1 >= 0) {
                float gate = g_gate[r1];
                g_zf[(size_t)r1*256 + c0] = rnd_tf(g_z[(size_t)r1*256 + c0] + gate*(acc[mi][ni][2] + eb2[e*256 + c0]));
                g_zf[(size_t)r1*256 + c1] = rnd_tf(g_z[(size_t)r1*256 + c1] + gate*(acc[mi][ni][3] + eb2[e*256 + c1]));
            }
        }
}

__global__ void __launch_bounds__(NTHREADS, 2)
k_tpre(const float* __restrict__ b) {
    extern __shared__ float sm[];
    float acc[4][4][4] = {};
    int m0 = blockIdx.y * BM, n0 = blockIdx.x * BN;
    gemm_tf32<false>(acc, g_zf, 256, 256, g_w_gd1, 256, m0, n0, nullptr, sm);
    FRAG_IDX
    #pragma unroll
    for (int mi = 0; mi < 4; mi++)
        #pragma unroll
        for (int ni = 0; ni < 4; ni++) {
            int r0 = m0 + mw + mi*16 + g, r1 = r0 + 8;
            int c0 = n0 + nw + ni*8 + t4*2, c1 = c0 + 1;
            g_tpre[(size_t)r0*256 + c0] = acc[mi][ni][0] + b[c0];
            g_tpre[(size_t)r0*256 + c1] = acc[mi][ni][1] + b[c1];
            g_tpre[(size_t)r1*256 + c0] = acc[mi][ni][2] + b[c0];
            g_tpre[(size_t)r1*256 + c1] = acc[mi][ni][3] + b[c1];
        }
}

__global__ void k_ln(const float* __restrict__ gam, const float* __restrict__ beta) {
    int w = threadIdx.x >> 5, lane = threadIdx.x & 31;
    int row = blockIdx.x * 8 + w;
    float v[8]; float s = 0.f;
    #pragma unroll
    for (int i = 0; i < 8; i++) {
        v[i] = g_tpre[(size_t)row*256 + lane + 32*i];
        s += v[i];
    }
    #pragma unroll
    for (int off = 16; off; off >>= 1) s += __shfl_xor_sync(0xffffffffu, s, off);
    float mean = s * (1.f/256.f);
    float s2 = 0.f;
    #pragma unroll
    for (int i = 0; i < 8; i++) { float d = v[i] - mean; s2 = fmaf(d, d, s2); }
    #pragma unroll
    for (int off = 16; off; off >>= 1) s2 += __shfl_xor_sync(0xffffffffu, s2, off);
    float rs = rsqrtf(s2 * (1.f/256.f) + 1e-5f);
    #pragma unroll
    for (int i = 0; i < 8; i++) {
        int k = lane + 32*i;
        g_t[(size_t)row*256 + k] = rnd_tf(gelu_exact(gam[k] * (v[i] - mean) * rs + beta[k]));
    }
}

// gd2 with smem-staged, fully coalesced epilogue.
__global__ void __launch_bounds__(NTHREADS, 2)
k_gd2(const float* __restrict__ b2,
      const float* __restrict__ lib, float* __restrict__ out) {
    extern __shared__ float sm[];
    float acc[4][4][4] = {};
    int m0 = blockIdx.y * BM, n0 = blockIdx.x * BN;
    gemm_tf32<false>(acc, g_t, 256, 256, g_w_gd2, N_GD2, m0, n0, nullptr, sm);
    FRAG_IDX
    // stage acc tile into smem (gemm's trailing sync makes sm free)
    float* es = sm;
    #pragma unroll
    for (int mi = 0; mi < 4; mi++)
        #pragma unroll
        for (int ni = 0; ni < 4; ni++) {
            int r0 = mw + mi*16 + g, r1 = r0 + 8;
            int c0 = nw + ni*8 + t4*2, c1 = c0 + 1;
            es[r0*ES_STRIDE + c0] = acc[mi][ni][0];
            es[r0*ES_STRIDE + c1] = acc[mi][ni][1];
            es[r1*ES_STRIDE + c0] = acc[mi][ni][2];
            es[r1*ES_STRIDE + c1] = acc[mi][ni][3];
        }
    __syncthreads();
    // coalesced emit: warp lanes cover 32 consecutive gi per store
    const size_t THETA_OFF = (size_t)B_ROWS * G_NUM;
    int gbase = n0 >> 1;
    for (int r = warp; r < BM; r += 8) {
        int row = m0 + r;
        float lb = lib[row];
        #pragma unroll
        for (int j = 0; j < 2; j++) {
            int gcol = j*32 + lane;          // gi within tile, 0..63
            int col0 = 2*gcol, col1 = col0 + 1;
            if (n0 + col0 < N_GD2) {
                float v = es[r*ES_STRIDE + col0] + b2[n0 + col0];
                float sp = (v > 20.f) ? v : log1pf(expf(v));
                out[(size_t)row*G_NUM + gbase + gcol] = sp * lb + 1e-6f;
            }
            if (n0 + col1 < N_GD2) {
                float v = es[r*ES_STRIDE + col1] + b2[n0 + col1];
                float sp = (v > 20.f) ? v : log1pf(expf(v));
                out[THETA_OFF + (size_t)row*G_NUM + gbase + gcol] = sp + 1e-6f;
            }
        }
    }
}

// merged align + func hidden: N=192 packed weights
__global__ void __launch_bounds__(NTHREADS, 2)
k_apfh(const float* __restrict__ apb, const float* __restrict__ fhb) {
    extern __shared__ float sm[];
    float acc[4][4][4] = {};
    int m0 = blockIdx.y * BM, n0 = blockIdx.x * BN;
    gemm_tf32<false>(acc, g_zf, 256, 256, g_w_apfh, 192, m0, n0, nullptr, sm);
    FRAG_IDX
    #pragma unroll
    for (int mi = 0; mi < 4; mi++)
        #pragma unroll
        for (int ni = 0; ni < 4; ni++) {
            int r0 = m0 + mw + mi*16 + g, r1 = r0 + 8;
            int c0 = n0 + nw + ni*8 + t4*2, c1 = c0 + 1;
            #pragma unroll
            for (int q = 0; q < 4; q++) {
                int r = (q & 2) ? r1 : r0;
                int c = (q & 1) ? c1 : c0;
                float v = acc[mi][ni][q];
                if (c < 128)
                    g_a1[(size_t)r*128 + c] = gelu_exact(v + apb[c]);
                else if (c < 192)
                    g_f1[(size_t)r*64 + (c - 128)] = gelu_exact(v + fhb[c - 128]);
            }
        }
}

__global__ void k_ap2(const float* __restrict__ W2, const float* __restrict__ b2,
                      float* __restrict__ out) {
    __shared__ float Ws[128*SCVI_];
    __shared__ float bs[SCVI_];
    for (int i = threadIdx.x; i < 128*SCVI_; i += 256) Ws[i] = W2[i];
    if (threadIdx.x < SCVI_) bs[threadIdx.x] = b2[threadIdx.x];
    __syncthreads();
    int w = threadIdx.x >> 5, lane = threadIdx.x & 31;
    int row = blockIdx.x * 8 + w;
    float a[4];
    #pragma unroll
    for (int i = 0; i < 4; i++) a[i] = g_a1[(size_t)row*128 + lane + 32*i];
    const size_t ALIGN_OFF = 2ull * B_ROWS * G_NUM + B_ROWS;
    for (int c = 0; c < SCVI_; c++) {
        float s = 0.f;
        #pragma unroll
        for (int i = 0; i < 4; i++) s = fmaf(a[i], Ws[(lane + 32*i)*SCVI_ + c], s);
        #pragma unroll
        for (int off = 16; off; off >>= 1) s += __shfl_down_sync(0xffffffffu, s, off);
        if (lane == 0) out[ALIGN_OFF + (size_t)row*SCVI_ + c] = s + bs[c];
    }
}

__global__ void k_fh2(const float* __restrict__ W2, const float* __restrict__ b2,
                      float* __restrict__ out) {
    int w = threadIdx.x >> 5, lane = threadIdx.x & 31;
    int row = blockIdx.x * 8 + w;
    float v = g_f1[(size_t)row*64 + lane] * W2[lane]
            + g_f1[(size_t)row*64 + lane + 32] * W2[lane + 32];
    #pragma unroll
    for (int off = 16; off; off >>= 1) v += __shfl_down_sync(0xffffffffu, v, off);
    if (lane == 0) {
        const size_t FUNC_OFF = 2ull * B_ROWS * G_NUM;
        out[FUNC_OFF + row] = 1.f / (1.f + expf(-(v + b2[0])));
    }
}

// ---------------- launch ----------------
extern "C" void kernel_launch(void* const* d_in, const int* in_sizes, int n_in,
                              void* d_out, int out_size) {
    const float* vis   = (const float*)d_in[0];
    const float* pos   = (const float*)d_in[1];
    const float* grad  = (const float*)d_in[2];
    const float* lib   = (const float*)d_in[3];
    const float* fB    = (const float*)d_in[4];
    const float* img_W = (const float*)d_in[5];
    const float* img_b = (const float*)d_in[6];
    const float* pos_W = (const float*)d_in[7];
    const float* pos_b = (const float*)d_in[8];
    const float* rW    = (const float*)d_in[9];
    const float* rb    = (const float*)d_in[10];
    const float* eW1   = (const float*)d_in[11];
    const float* eb1   = (const float*)d_in[12];
    const float* eW2   = (const float*)d_in[13];
    const float* eb2   = (const float*)d_in[14];
    const float* gdW1  = (const float*)d_in[15];
    const float* gdb1  = (const float*)d_in[16];
    const float* gdg   = (const float*)d_in[17];
    const float* gdbe  = (const float*)d_in[18];
    const float* gdW2  = (const float*)d_in[19];
    const float* gdb2  = (const float*)d_in[20];
    const float* apW1  = (const float*)d_in[21];
    const float* apb1  = (const float*)d_in[22];
    const float* apW2  = (const float*)d_in[23];
    const float* apb2  = (const float*)d_in[24];
    const float* fhW1  = (const float*)d_in[25];
    const float* fhb1  = (const float*)d_in[26];
    const float* fhW2  = (const float*)d_in[27];
    const float* fhb2  = (const float*)d_in[28];
    float* out = (float*)d_out;

    static const int SM = SMEM_BYTES;
    cudaFuncSetAttribute(k_gemm_z, cudaFuncAttributeMaxDynamicSharedMemorySize, SM);
    cudaFuncSetAttribute(k_moe1,   cudaFuncAttributeMaxDynamicSharedMemorySize, SM);
    cudaFuncSetAttribute(k_moe2,   cudaFuncAttributeMaxDynamicSharedMemorySize, SM);
    cudaFuncSetAttribute(k_tpre,   cudaFuncAttributeMaxDynamicSharedMemorySize, SM);
    cudaFuncSetAttribute(k_gd2,    cudaFuncAttributeMaxDynamicSharedMemorySize, SM);
    cudaFuncSetAttribute(k_apfh,   cudaFuncAttributeMaxDynamicSharedMemorySize, SM);

    k_round_all<<<(RC7 + 255)/256, 256>>>(pos_W, img_W, eW1, eW2, gdW1, gdW2, apW1, fhW1);

    k_four   <<<B_ROWS/8, 256>>>(pos, fB);
    k_gemm_z <<<dim3(2, B_ROWS/BM), NTHREADS, SM>>>(vis, img_b, pos_b);
    k_router <<<B_ROWS/8, 256>>>(grad, rW, rb);
    k_offsets<<<1,1>>>();
    k_scatter<<<B_ROWS/256, 256>>>();
    k_moe1   <<<dim3(8, MAX_TILES), NTHREADS, SM>>>(eb1);
    k_moe2   <<<dim3(2, MAX_TILES), NTHREADS, SM>>>(eb2);
    k_tpre   <<<dim3(2, B_ROWS/BM), NTHREADS, SM>>>(gdb1);
    k_ln     <<<B_ROWS/8, 256>>>(gdg, gdbe);
    k_gd2    <<<dim3((N_GD2 + BN - 1)/BN, B_ROWS/BM), NTHREADS, SM>>>(gdb2, lib, out);
    k_apfh   <<<dim3(2, B_ROWS/BM), NTHREADS, SM>>>(apb1, fhb1);
    k_ap2    <<<B_ROWS/8, 256>>>(apW2, apb2, out);
    k_fh2    <<<B_ROWS/8, 256>>>(fhW2, fhb2, out);
}